// round 5
// baseline (speedup 1.0000x reference)
#include <cuda_runtime.h>
#include <cstdint>

// Problem constants
#define Bb 2
#define Nn 100000
#define Ff 64
#define Ee 800000
#define EO 16
#define NO 64

// Scratch (device globals — no allocation allowed)
__device__ float g_P[Bb * Nn * 32];    // [b][n][0:16]=x·W1, [16:32]=x·W2
__device__ float g_agg[Bb * Nn * 16];  // aggregation buffer

// ---------------------------------------------------------------------------
// Packed fp32x2 helpers (Blackwell sm_100+; ptxas never emits these from C++)
// ---------------------------------------------------------------------------
__device__ __forceinline__ unsigned long long pack2(float a, float b) {
    unsigned long long r;
    asm("mov.b64 %0, {%1, %2};" : "=l"(r) : "f"(a), "f"(b));
    return r;
}
__device__ __forceinline__ float2 unpack2(unsigned long long v) {
    float2 r;
    asm("mov.b64 {%0, %1}, %2;" : "=f"(r.x), "=f"(r.y) : "l"(v));
    return r;
}
__device__ __forceinline__ unsigned long long fma2(unsigned long long a,
                                                   unsigned long long b,
                                                   unsigned long long c) {
    unsigned long long d;
    asm("fma.rn.f32x2 %0, %1, %2, %3;" : "=l"(d) : "l"(a), "l"(b), "l"(c));
    return d;
}

// ---------------------------------------------------------------------------
// MUFU sigmoid: 2 MUFU + 2 FMA-pipe ops; MUFU pipe otherwise idle.
// ---------------------------------------------------------------------------
__device__ __forceinline__ float sigmoid_mufu(float x) {
    float e, r;
    asm("ex2.approx.ftz.f32 %0, %1;" : "=f"(e) : "f"(x * -1.4426950408889634f));
    asm("rcp.approx.ftz.f32 %0, %1;" : "=f"(r) : "f"(1.0f + e));
    return r;
}

// No-memory-clobber vectored reduction: asm volatile keeps it issued, but
// WITHOUT the "memory" clobber subsequent iterations' loads may be hoisted
// above it (g_agg is never read in this kernel, so no aliasing hazard).
__device__ __forceinline__ void red_v4(float* p, float a, float b, float c, float d) {
    asm volatile("red.global.add.v4.f32 [%0], {%1,%2,%3,%4};"
                 :: "l"(p), "f"(a), "f"(b), "f"(c), "f"(d));
}

// ---------------------------------------------------------------------------
// K1: zero g_agg, then P[b,n,j] = sum_k x[b,n,k] * W1/W2[k,j].
// Warp processes two nodes per iteration (4 independent fma2 chains, one
// __syncwarp per pair, double-buffered smem). __launch_bounds__(128,5)
// caps regs ~102 -> 5 CTAs = 20 warps/SM (was 16 at 104 regs).
// ---------------------------------------------------------------------------
__global__ __launch_bounds__(128, 5) void k1_precompute(
    const float* __restrict__ x, const float* __restrict__ W_e) {
    __shared__ float xs[4][2][128];   // [warp][buf][2 node rows]

    const int tid = blockIdx.x * blockDim.x + threadIdx.x;
    const int nth = gridDim.x * blockDim.x;

    // Zero the aggregation buffer (vectorized)
    const float4 z4 = make_float4(0.f, 0.f, 0.f, 0.f);
    for (int i = tid; i < (Bb * Nn * 16) / 4; i += nth)
        ((float4*)g_agg)[i] = z4;

    const int lane  = threadIdx.x & 31;
    const int winb  = threadIdx.x >> 5;
    const int col   = lane & 15;
    const int rbase = (lane >= 16) ? 64 : 0;    // lanes 16..31 -> W2 rows

    // Pre-packed weight pairs: w2[k] = {W[2k][col], W[2k+1][col]}
    unsigned long long w2[32];
#pragma unroll
    for (int k = 0; k < 32; k++)
        w2[k] = pack2(__ldg(W_e + (rbase + 2 * k) * EO + col),
                      __ldg(W_e + (rbase + 2 * k + 1) * EO + col));

    const uint32_t sb0 = (uint32_t)__cvta_generic_to_shared(&xs[winb][0][0]);
    const uint32_t sb1 = (uint32_t)__cvta_generic_to_shared(&xs[winb][1][0]);

    const int warpId = tid >> 5;
    const int nwarps = nth >> 5;
    int p = 0;
    for (int pair = warpId; pair < (Bb * Nn) / 2; pair += nwarps) {
        const float4 xv = ((const float4*)(x + (size_t)pair * 128))[lane];
        const uint32_t sb = p ? sb1 : sb0;
        ((float4*)(p ? xs[winb][1] : xs[winb][0]))[lane] = xv;
        __syncwarp();

        unsigned long long accA0 = 0ull, accB0 = 0ull;
        unsigned long long accA1 = 0ull, accB1 = 0ull;
#pragma unroll
        for (int kk = 0; kk < 16; kk++) {
            unsigned long long a0, a1, b0, b1;
            asm volatile("ld.shared.v2.b64 {%0, %1}, [%2];"
                         : "=l"(a0), "=l"(a1) : "r"(sb + kk * 16));
            asm volatile("ld.shared.v2.b64 {%0, %1}, [%2];"
                         : "=l"(b0), "=l"(b1) : "r"(sb + 256 + kk * 16));
            accA0 = fma2(a0, w2[2 * kk],     accA0);
            accB0 = fma2(a1, w2[2 * kk + 1], accB0);
            accA1 = fma2(b0, w2[2 * kk],     accA1);
            accB1 = fma2(b1, w2[2 * kk + 1], accB1);
        }

        float2 sA0 = unpack2(accA0), sB0 = unpack2(accB0);
        float2 sA1 = unpack2(accA1), sB1 = unpack2(accB1);
        g_P[(size_t)pair * 64 + lane]      = (sA0.x + sA0.y) + (sB0.x + sB0.y);
        g_P[(size_t)pair * 64 + 32 + lane] = (sA1.x + sA1.y) + (sB1.x + sB1.y);
        p ^= 1;   // double buffer: no trailing sync needed
    }
}

// ---------------------------------------------------------------------------
// K2: per edge-instance (b,e): h = sigmoid(P1[src] + P2[tgt] + ew*w3 + b_e),
// then agg[tgt] += h, agg[src] -= h.
// TWO threads per edge-instance; thread q in {0,1} owns floats [8q, 8q+8):
// 4 independent 16B nc gathers per iteration (2x the MLP of the 4-thread
// version), half the redundant index loads. REDs carry no memory clobber so
// the unrolled next iteration's loads pipeline above them.
// ---------------------------------------------------------------------------
__global__ __launch_bounds__(256) void k2_edges(
    const int* __restrict__ esrc, const int* __restrict__ etgt,
    const float* __restrict__ ew, const float* __restrict__ W_e,
    const float* __restrict__ b_e) {
    const int tid0 = blockIdx.x * blockDim.x + threadIdx.x;
    const int nth  = gridDim.x * blockDim.x;   // even -> q invariant
    const int q    = tid0 & 1;

    const float4 w3a = ((const float4*)(W_e + 128 * EO))[2 * q];
    const float4 w3b = ((const float4*)(W_e + 128 * EO))[2 * q + 1];
    const float4 bqa = ((const float4*)b_e)[2 * q];
    const float4 bqb = ((const float4*)b_e)[2 * q + 1];

#pragma unroll 1
    for (int b = 0; b < Bb; b++) {
        const float* Pb = g_P + (size_t)b * Nn * 32;
        float* aggb     = g_agg + (size_t)b * Nn * 16;

#pragma unroll 2
        for (int gid = tid0; gid < Ee * 2; gid += nth) {
            const int e = gid >> 1;

            const int   s  = __ldg(esrc + e);
            const int   t  = __ldg(etgt + e);
            const float wv = __ldg(ew + e);

            const float4* P1 = (const float4*)(Pb + (size_t)s * 32 + q * 8);
            const float4* P2 = (const float4*)(Pb + (size_t)t * 32 + 16 + q * 8);
            const float4 p1a = __ldg(P1);
            const float4 p1b = __ldg(P1 + 1);
            const float4 p2a = __ldg(P2);
            const float4 p2b = __ldg(P2 + 1);

            float4 ha, hb;
            ha.x = sigmoid_mufu(fmaf(wv, w3a.x, p1a.x + p2a.x + bqa.x));
            ha.y = sigmoid_mufu(fmaf(wv, w3a.y, p1a.y + p2a.y + bqa.y));
            ha.z = sigmoid_mufu(fmaf(wv, w3a.z, p1a.z + p2a.z + bqa.z));
            ha.w = sigmoid_mufu(fmaf(wv, w3a.w, p1a.w + p2a.w + bqa.w));
            hb.x = sigmoid_mufu(fmaf(wv, w3b.x, p1b.x + p2b.x + bqb.x));
            hb.y = sigmoid_mufu(fmaf(wv, w3b.y, p1b.y + p2b.y + bqb.y));
            hb.z = sigmoid_mufu(fmaf(wv, w3b.z, p1b.z + p2b.z + bqb.z));
            hb.w = sigmoid_mufu(fmaf(wv, w3b.w, p1b.w + p2b.w + bqb.w));

            float* ta = aggb + (size_t)t * 16 + q * 8;
            float* sa = aggb + (size_t)s * 16 + q * 8;
            red_v4(ta,     ha.x, ha.y, ha.z, ha.w);
            red_v4(ta + 4, hb.x, hb.y, hb.z, hb.w);
            red_v4(sa,     -ha.x, -ha.y, -ha.z, -ha.w);
            red_v4(sa + 4, -hb.x, -hb.y, -hb.z, -hb.w);
        }
    }
}

// ---------------------------------------------------------------------------
// K3: out[b,n,:] = sigmoid(agg[b,n,:16] @ W_n[16,64] + b_n). Warp per node;
// lane owns cols {lane, lane+32}; packed fma2; MUFU sigmoid.
// ---------------------------------------------------------------------------
__global__ __launch_bounds__(256) void k3_nodes(
    const float* __restrict__ W_n, const float* __restrict__ b_n,
    float* __restrict__ out) {
    const int lane = threadIdx.x & 31;

    unsigned long long wA2[8], wB2[8];
#pragma unroll
    for (int j = 0; j < 8; j++) {
        wA2[j] = pack2(__ldg(W_n + (2 * j) * NO + lane),
                       __ldg(W_n + (2 * j + 1) * NO + lane));
        wB2[j] = pack2(__ldg(W_n + (2 * j) * NO + lane + 32),
                       __ldg(W_n + (2 * j + 1) * NO + lane + 32));
    }
    const float bA = __ldg(b_n + lane);
    const float bB = __ldg(b_n + lane + 32);

    const int tid    = blockIdx.x * blockDim.x + threadIdx.x;
    const int warpId = tid >> 5;
    const int nwarps = (gridDim.x * blockDim.x) >> 5;

    for (int node = warpId; node < Bb * Nn; node += nwarps) {
        const float* ag = g_agg + (size_t)node * 16;
        unsigned long long a[8];
#pragma unroll
        for (int j = 0; j < 4; j++)
            asm volatile("ld.global.nc.v2.b64 {%0, %1}, [%2];"
                         : "=l"(a[2 * j]), "=l"(a[2 * j + 1])
                         : "l"(ag + 4 * j));

        unsigned long long accA = 0ull, accB = 0ull;
#pragma unroll
        for (int j = 0; j < 8; j++) {
            accA = fma2(a[j], wA2[j], accA);
            accB = fma2(a[j], wB2[j], accB);
        }
        float2 sA = unpack2(accA), sB = unpack2(accB);
        out[(size_t)node * NO + lane]      = sigmoid_mufu(bA + sA.x + sA.y);
        out[(size_t)node * NO + lane + 32] = sigmoid_mufu(bB + sB.x + sB.y);
    }
}

// ---------------------------------------------------------------------------
extern "C" void kernel_launch(void* const* d_in, const int* in_sizes, int n_in,
                              void* d_out, int out_size) {
    const float* x    = (const float*)d_in[0];
    const int*   esrc = (const int*)d_in[1];
    const int*   etgt = (const int*)d_in[2];
    const float* ew   = (const float*)d_in[3];
    const float* W_e  = (const float*)d_in[4];
    const float* b_e  = (const float*)d_in[5];
    const float* W_n  = (const float*)d_in[6];
    const float* b_n  = (const float*)d_in[7];
    float* out = (float*)d_out;

    k1_precompute<<<148 * 16, 128>>>(x, W_e);
    k2_edges<<<148 * 8, 256>>>(esrc, etgt, ew, W_e, b_e);
    k3_nodes<<<148 * 8, 256>>>(W_n, b_n, out);
}

// round 6
// speedup vs baseline: 1.1070x; 1.1070x over previous
#include <cuda_runtime.h>
#include <cstdint>

// Problem constants
#define Bb 2
#define Nn 100000
#define Ff 64
#define Ee 800000
#define EO 16
#define NO 64

// Scratch (device globals — no allocation allowed)
__device__ float g_P[Bb * Nn * 32];    // [b][n][0:16]=x·W1, [16:32]=x·W2
__device__ float g_agg[Bb * Nn * 16];  // aggregation buffer

// ---------------------------------------------------------------------------
// Packed fp32x2 helpers (Blackwell sm_100+; ptxas never emits these from C++)
// ---------------------------------------------------------------------------
__device__ __forceinline__ unsigned long long pack2(float a, float b) {
    unsigned long long r;
    asm("mov.b64 %0, {%1, %2};" : "=l"(r) : "f"(a), "f"(b));
    return r;
}
__device__ __forceinline__ float2 unpack2(unsigned long long v) {
    float2 r;
    asm("mov.b64 {%0, %1}, %2;" : "=f"(r.x), "=f"(r.y) : "l"(v));
    return r;
}
__device__ __forceinline__ unsigned long long fma2(unsigned long long a,
                                                   unsigned long long b,
                                                   unsigned long long c) {
    unsigned long long d;
    asm("fma.rn.f32x2 %0, %1, %2, %3;" : "=l"(d) : "l"(a), "l"(b), "l"(c));
    return d;
}

// ---------------------------------------------------------------------------
// MUFU sigmoid: 2 MUFU + 2 FMA-pipe ops; MUFU pipe otherwise idle.
// ---------------------------------------------------------------------------
__device__ __forceinline__ float sigmoid_mufu(float x) {
    float e, r;
    asm("ex2.approx.ftz.f32 %0, %1;" : "=f"(e) : "f"(x * -1.4426950408889634f));
    asm("rcp.approx.ftz.f32 %0, %1;" : "=f"(r) : "f"(1.0f + e));
    return r;
}

// ---------------------------------------------------------------------------
// K1: zero g_agg, then P[b,n,j] = sum_k x[b,n,k] * W1/W2[k,j].
// K1 is LDS-ISSUE-RATE bound (round-5 evidence: +5% occ -> 0% speedup;
// 16 LDS.128/node x 4cyc/SM floor == measured 46us). Fix: halve LDS ops.
// New mapping: warp covers 2 nodes; lanes 0-15 own node0, lanes 16-31 own
// node1. Each lane computes BOTH the W1 and W2 column `lane&15` of its node
// (128 weight floats in regs). One ld.shared.v2.b64 per kk now serves both
// nodes (half-dependent address, conflict degree 2 = free): 8 LDS/node
// instead of 16. fma2 count unchanged (32/node = the FMA floor).
// ---------------------------------------------------------------------------
__global__ __launch_bounds__(128) void k1_precompute(
    const float* __restrict__ x, const float* __restrict__ W_e) {
    __shared__ float xs[4][2][128];   // [warp][buf][node0 row | node1 row]

    const int tid = blockIdx.x * blockDim.x + threadIdx.x;
    const int nth = gridDim.x * blockDim.x;

    // Zero the aggregation buffer (vectorized)
    const float4 z4 = make_float4(0.f, 0.f, 0.f, 0.f);
    for (int i = tid; i < (Bb * Nn * 16) / 4; i += nth)
        ((float4*)g_agg)[i] = z4;

    const int lane = threadIdx.x & 31;
    const int winb = threadIdx.x >> 5;
    const int half = lane >> 4;        // 0: node0, 1: node1
    const int col  = lane & 15;        // owned output column (both W1 and W2)

    // Weights for this column, packed by k-pairs:
    //   wa2[k] = {W1[2k][col], W1[2k+1][col]}   (W_e rows 0..63)
    //   wb2[k] = {W2[2k][col], W2[2k+1][col]}   (W_e rows 64..127)
    unsigned long long wa2[32], wb2[32];
#pragma unroll
    for (int k = 0; k < 32; k++) {
        wa2[k] = pack2(__ldg(W_e + (2 * k) * EO + col),
                       __ldg(W_e + (2 * k + 1) * EO + col));
        wb2[k] = pack2(__ldg(W_e + (64 + 2 * k) * EO + col),
                       __ldg(W_e + (64 + 2 * k + 1) * EO + col));
    }

    const uint32_t sb0 = (uint32_t)__cvta_generic_to_shared(&xs[winb][0][0]);
    const uint32_t sb1 = (uint32_t)__cvta_generic_to_shared(&xs[winb][1][0]);
    const uint32_t hoff = (uint32_t)half * 256;   // my node's row offset

    const int warpId = tid >> 5;
    const int nwarps = nth >> 5;
    int p = 0;
    for (int pair = warpId; pair < (Bb * Nn) / 2; pair += nwarps) {
        // Load two consecutive node rows (512B) with one LDG.128 per lane.
        const float4 xv = ((const float4*)(x + (size_t)pair * 128))[lane];
        ((float4*)(p ? xs[winb][1] : xs[winb][0]))[lane] = xv;
        __syncwarp();
        const uint32_t sb = (p ? sb1 : sb0) + hoff;

        unsigned long long accA0 = 0ull, accA1 = 0ull;  // W1 col, even/odd kk
        unsigned long long accB0 = 0ull, accB1 = 0ull;  // W2 col
#pragma unroll
        for (int kk = 0; kk < 16; kk++) {
            unsigned long long a0, a1;   // {x[4kk],x[4kk+1]}, {x[4kk+2],x[4kk+3]}
            asm volatile("ld.shared.v2.b64 {%0, %1}, [%2];"
                         : "=l"(a0), "=l"(a1) : "r"(sb + kk * 16));
            accA0 = fma2(a0, wa2[2 * kk],     accA0);
            accA1 = fma2(a1, wa2[2 * kk + 1], accA1);
            accB0 = fma2(a0, wb2[2 * kk],     accB0);
            accB1 = fma2(a1, wb2[2 * kk + 1], accB1);
        }

        const float2 sA0 = unpack2(accA0), sA1 = unpack2(accA1);
        const float2 sB0 = unpack2(accB0), sB1 = unpack2(accB1);
        const int node = pair * 2 + half;
        g_P[(size_t)node * 32 + col]      = (sA0.x + sA0.y) + (sA1.x + sA1.y);
        g_P[(size_t)node * 32 + 16 + col] = (sB0.x + sB0.y) + (sB1.x + sB1.y);
        p ^= 1;   // double buffer: no trailing WAR sync needed
    }
}

// ---------------------------------------------------------------------------
// K2: per edge-instance (b,e): h = sigmoid(P1[src] + P2[tgt] + ew*w3 + b_e),
// then agg[tgt] += h, agg[src] -= h via red.global.add.v4.f32.
// 4 threads per edge-instance, thread q owns output quad q. Sigmoids on MUFU.
// (Exact revert to the proven round-4 form; the 2-thread/no-clobber variant
// regressed 17us.)
// ---------------------------------------------------------------------------
__global__ __launch_bounds__(256) void k2_edges(
    const int* __restrict__ esrc, const int* __restrict__ etgt,
    const float* __restrict__ ew, const float* __restrict__ W_e,
    const float* __restrict__ b_e) {
    const int tid0 = blockIdx.x * blockDim.x + threadIdx.x;
    const int nth  = gridDim.x * blockDim.x;   // multiple of 4 -> q invariant
    const int q    = tid0 & 3;

    const float4 w3 = ((const float4*)(W_e + 128 * EO))[q];  // ew row
    const float4 bq = ((const float4*)b_e)[q];

#pragma unroll 1
    for (int b = 0; b < Bb; b++) {
        const float* Pb = g_P + (size_t)b * Nn * 32;
        float* aggb     = g_agg + (size_t)b * Nn * 16;

        for (int gid = tid0; gid < Ee * 4; gid += nth) {
            const int e = gid >> 2;

            const int   s  = __ldg(esrc + e);
            const int   t  = __ldg(etgt + e);
            const float wv = __ldg(ew + e);

            const float4 p1 = __ldg((const float4*)(Pb + (size_t)s * 32 + q * 4));
            const float4 p2 = __ldg((const float4*)(Pb + (size_t)t * 32 + 16 + q * 4));

            float4 h;
            h.x = sigmoid_mufu(fmaf(wv, w3.x, p1.x + p2.x + bq.x));
            h.y = sigmoid_mufu(fmaf(wv, w3.y, p1.y + p2.y + bq.y));
            h.z = sigmoid_mufu(fmaf(wv, w3.z, p1.z + p2.z + bq.z));
            h.w = sigmoid_mufu(fmaf(wv, w3.w, p1.w + p2.w + bq.w));

            float* ta = aggb + (size_t)t * 16 + q * 4;
            float* sa = aggb + (size_t)s * 16 + q * 4;
            asm volatile("red.global.add.v4.f32 [%0], {%1,%2,%3,%4};"
                         :: "l"(ta), "f"(h.x), "f"(h.y), "f"(h.z), "f"(h.w) : "memory");
            asm volatile("red.global.add.v4.f32 [%0], {%1,%2,%3,%4};"
                         :: "l"(sa), "f"(-h.x), "f"(-h.y), "f"(-h.z), "f"(-h.w) : "memory");
        }
    }
}

// ---------------------------------------------------------------------------
// K3: out[b,n,:] = sigmoid(agg[b,n,:16] @ W_n[16,64] + b_n). Warp per node;
// lane owns cols {lane, lane+32}; packed fma2; MUFU sigmoid.
// ---------------------------------------------------------------------------
__global__ __launch_bounds__(256) void k3_nodes(
    const float* __restrict__ W_n, const float* __restrict__ b_n,
    float* __restrict__ out) {
    const int lane = threadIdx.x & 31;

    unsigned long long wA2[8], wB2[8];
#pragma unroll
    for (int j = 0; j < 8; j++) {
        wA2[j] = pack2(__ldg(W_n + (2 * j) * NO + lane),
                       __ldg(W_n + (2 * j + 1) * NO + lane));
        wB2[j] = pack2(__ldg(W_n + (2 * j) * NO + lane + 32),
                       __ldg(W_n + (2 * j + 1) * NO + lane + 32));
    }
    const float bA = __ldg(b_n + lane);
    const float bB = __ldg(b_n + lane + 32);

    const int tid    = blockIdx.x * blockDim.x + threadIdx.x;
    const int warpId = tid >> 5;
    const int nwarps = (gridDim.x * blockDim.x) >> 5;

    for (int node = warpId; node < Bb * Nn; node += nwarps) {
        const float* ag = g_agg + (size_t)node * 16;
        unsigned long long a[8];
#pragma unroll
        for (int j = 0; j < 4; j++)
            asm volatile("ld.global.nc.v2.b64 {%0, %1}, [%2];"
                         : "=l"(a[2 * j]), "=l"(a[2 * j + 1])
                         : "l"(ag + 4 * j));

        unsigned long long accA = 0ull, accB = 0ull;
#pragma unroll
        for (int j = 0; j < 8; j++) {
            accA = fma2(a[j], wA2[j], accA);
            accB = fma2(a[j], wB2[j], accB);
        }
        float2 sA = unpack2(accA), sB = unpack2(accB);
        out[(size_t)node * NO + lane]      = sigmoid_mufu(bA + sA.x + sA.y);
        out[(size_t)node * NO + lane + 32] = sigmoid_mufu(bB + sB.x + sB.y);
    }
}

// ---------------------------------------------------------------------------
extern "C" void kernel_launch(void* const* d_in, const int* in_sizes, int n_in,
                              void* d_out, int out_size) {
    const float* x    = (const float*)d_in[0];
    const int*   esrc = (const int*)d_in[1];
    const int*   etgt = (const int*)d_in[2];
    const float* ew   = (const float*)d_in[3];
    const float* W_e  = (const float*)d_in[4];
    const float* b_e  = (const float*)d_in[5];
    const float* W_n  = (const float*)d_in[6];
    const float* b_n  = (const float*)d_in[7];
    float* out = (float*)d_out;

    k1_precompute<<<148 * 16, 128>>>(x, W_e);
    k2_edges<<<148 * 8, 256>>>(esrc, etgt, ew, W_e, b_e);
    k3_nodes<<<148 * 8, 256>>>(W_n, b_n, out);
}

// round 7
// speedup vs baseline: 1.2083x; 1.0915x over previous
#include <cuda_runtime.h>
#include <cstdint>

// Problem constants
#define Bb 2
#define Nn 100000
#define Ff 64
#define Ee 800000
#define EO 16
#define NO 64

// Scratch (device globals — no allocation allowed)
__device__ float g_P[Bb * Nn * 32];    // [b][n][0:16]=x·W1, [16:32]=x·W2
__device__ float g_agg[Bb * Nn * 16];  // aggregation buffer

// ---------------------------------------------------------------------------
// Packed fp32x2 helpers (Blackwell sm_100+)
// ---------------------------------------------------------------------------
__device__ __forceinline__ unsigned long long pack2(float a, float b) {
    unsigned long long r;
    asm("mov.b64 %0, {%1, %2};" : "=l"(r) : "f"(a), "f"(b));
    return r;
}
__device__ __forceinline__ float2 unpack2(unsigned long long v) {
    float2 r;
    asm("mov.b64 {%0, %1}, %2;" : "=f"(r.x), "=f"(r.y) : "l"(v));
    return r;
}
__device__ __forceinline__ unsigned long long fma2(unsigned long long a,
                                                   unsigned long long b,
                                                   unsigned long long c) {
    unsigned long long d;
    asm("fma.rn.f32x2 %0, %1, %2, %3;" : "=l"(d) : "l"(a), "l"(b), "l"(c));
    return d;
}

// ---------------------------------------------------------------------------
// MUFU sigmoid: 2 MUFU + 2 FMA-pipe ops; MUFU pipe otherwise idle.
// ---------------------------------------------------------------------------
__device__ __forceinline__ float sigmoid_mufu(float x) {
    float e, r;
    asm("ex2.approx.ftz.f32 %0, %1;" : "=f"(e) : "f"(x * -1.4426950408889634f));
    asm("rcp.approx.ftz.f32 %0, %1;" : "=f"(r) : "f"(1.0f + e));
    return r;
}

// ---------------------------------------------------------------------------
// K1: zero g_agg, then P[b,n,j] = sum_k x[b,n,k] * W1/W2[k,j].
// K1 is LDG-LATENCY bound (rounds 4-6: LDS halving and occ changes were both
// no-ops; HBM stuck at 1.2TB/s on a sequential stream = MLP starvation).
// Fix: 2-deep software prefetch of the x rows — two float4 per warp in
// flight, issued two iterations ahead of consumption. Mapping is the proven
// round-4 one (104 regs): lane owns (W1|W2, col lane&15); warp covers 2
// nodes/iter with 4 independent fma2 chains; double-buffered smem.
// ---------------------------------------------------------------------------
__global__ __launch_bounds__(128) void k1_precompute(
    const float* __restrict__ x, const float* __restrict__ W_e) {
    __shared__ float xs[4][2][128];   // [warp][buf][2 node rows]

    const int tid = blockIdx.x * blockDim.x + threadIdx.x;
    const int nth = gridDim.x * blockDim.x;

    // Zero the aggregation buffer (vectorized)
    const float4 z4 = make_float4(0.f, 0.f, 0.f, 0.f);
    for (int i = tid; i < (Bb * Nn * 16) / 4; i += nth)
        ((float4*)g_agg)[i] = z4;

    const int lane  = threadIdx.x & 31;
    const int winb  = threadIdx.x >> 5;
    const int col   = lane & 15;
    const int rbase = (lane >= 16) ? 64 : 0;    // lanes 16..31 -> W2 rows

    // Pre-packed weight pairs: w2[k] = {W[2k][col], W[2k+1][col]}
    unsigned long long w2[32];
#pragma unroll
    for (int k = 0; k < 32; k++)
        w2[k] = pack2(__ldg(W_e + (rbase + 2 * k) * EO + col),
                      __ldg(W_e + (rbase + 2 * k + 1) * EO + col));

    const uint32_t sb0 = (uint32_t)__cvta_generic_to_shared(&xs[winb][0][0]);
    const uint32_t sb1 = (uint32_t)__cvta_generic_to_shared(&xs[winb][1][0]);

    const int NP     = (Bb * Nn) / 2;
    const int warpId = tid >> 5;
    const int nwarps = nth >> 5;

    // 2-deep prefetch pipeline (tail prefetches clamp to a valid row;
    // their values are never consumed).
    float4 xv0 = ((const float4*)(x + (size_t)warpId * 128))[lane];
    {
        const int pr1 = warpId + nwarps;
        const int c1  = pr1 < NP ? pr1 : NP - 1;
        float4 xv1 = ((const float4*)(x + (size_t)c1 * 128))[lane];

        int p = 0;
        for (int pair = warpId; pair < NP; pair += nwarps) {
            ((float4*)(p ? xs[winb][1] : xs[winb][0]))[lane] = xv0;
            __syncwarp();
            xv0 = xv1;
            const int pr2 = pair + 2 * nwarps;
            const int c2  = pr2 < NP ? pr2 : NP - 1;
            xv1 = ((const float4*)(x + (size_t)c2 * 128))[lane];  // 2 ahead

            const uint32_t sb = p ? sb1 : sb0;
            unsigned long long accA0 = 0ull, accB0 = 0ull;
            unsigned long long accA1 = 0ull, accB1 = 0ull;
#pragma unroll
            for (int kk = 0; kk < 16; kk++) {
                unsigned long long a0, a1, b0, b1;
                asm volatile("ld.shared.v2.b64 {%0, %1}, [%2];"
                             : "=l"(a0), "=l"(a1) : "r"(sb + kk * 16));
                asm volatile("ld.shared.v2.b64 {%0, %1}, [%2];"
                             : "=l"(b0), "=l"(b1) : "r"(sb + 256 + kk * 16));
                accA0 = fma2(a0, w2[2 * kk],     accA0);
                accB0 = fma2(a1, w2[2 * kk + 1], accB0);
                accA1 = fma2(b0, w2[2 * kk],     accA1);
                accB1 = fma2(b1, w2[2 * kk + 1], accB1);
            }

            const float2 sA0 = unpack2(accA0), sB0 = unpack2(accB0);
            const float2 sA1 = unpack2(accA1), sB1 = unpack2(accB1);
            g_P[(size_t)pair * 64 + lane]      = (sA0.x + sA0.y) + (sB0.x + sB0.y);
            g_P[(size_t)pair * 64 + 32 + lane] = (sA1.x + sA1.y) + (sB1.x + sB1.y);
            p ^= 1;
        }
    }
}

// ---------------------------------------------------------------------------
// K2: per edge-instance (b,e): h = sigmoid(P1[src] + P2[tgt] + ew*w3 + b_e),
// then agg[tgt] += h, agg[src] -= h via red.global.add.v4.f32.
// 4 threads/edge-instance (proven round-4 mapping) + 1-deep software
// prefetch: next iteration's indices AND P-gathers are issued before the
// current iteration's sigmoid/REDs, breaking the per-iteration serial chain
// (index ~200cyc -> gather ~250cyc -> RED) that the "memory" clobber
// otherwise forces end-to-end every iteration.
// ---------------------------------------------------------------------------
__global__ __launch_bounds__(256) void k2_edges(
    const int* __restrict__ esrc, const int* __restrict__ etgt,
    const float* __restrict__ ew, const float* __restrict__ W_e,
    const float* __restrict__ b_e) {
    const int tid0 = blockIdx.x * blockDim.x + threadIdx.x;
    const int nth  = gridDim.x * blockDim.x;   // multiple of 4 -> q invariant
    const int q    = tid0 & 3;

    const float4 w3 = ((const float4*)(W_e + 128 * EO))[q];  // ew row
    const float4 bq = ((const float4*)b_e)[q];

#pragma unroll 1
    for (int b = 0; b < Bb; b++) {
        const float* Pb = g_P + (size_t)b * Nn * 32;
        float* aggb     = g_agg + (size_t)b * Nn * 16;

        // Prologue: stage iteration 0.
        int   e  = tid0 >> 2;
        int   s  = __ldg(esrc + e);
        int   t  = __ldg(etgt + e);
        float wv = __ldg(ew + e);
        float4 p1 = __ldg((const float4*)(Pb + (size_t)s * 32 + q * 4));
        float4 p2 = __ldg((const float4*)(Pb + (size_t)t * 32 + 16 + q * 4));

        for (int gid = tid0; gid < Ee * 4; gid += nth) {
            // Prefetch next iteration (clamped at the tail; values unused).
            const int gidn = gid + nth;
            const int en   = (gidn < Ee * 4) ? (gidn >> 2) : e;
            const int   sn  = __ldg(esrc + en);
            const int   tn  = __ldg(etgt + en);
            const float wvn = __ldg(ew + en);
            const float4 p1n = __ldg((const float4*)(Pb + (size_t)sn * 32 + q * 4));
            const float4 p2n = __ldg((const float4*)(Pb + (size_t)tn * 32 + 16 + q * 4));

            // Current iteration's math + scatter.
            float4 h;
            h.x = sigmoid_mufu(fmaf(wv, w3.x, p1.x + p2.x + bq.x));
            h.y = sigmoid_mufu(fmaf(wv, w3.y, p1.y + p2.y + bq.y));
            h.z = sigmoid_mufu(fmaf(wv, w3.z, p1.z + p2.z + bq.z));
            h.w = sigmoid_mufu(fmaf(wv, w3.w, p1.w + p2.w + bq.w));

            float* ta = aggb + (size_t)t * 16 + q * 4;
            float* sa = aggb + (size_t)s * 16 + q * 4;
            asm volatile("red.global.add.v4.f32 [%0], {%1,%2,%3,%4};"
                         :: "l"(ta), "f"(h.x), "f"(h.y), "f"(h.z), "f"(h.w) : "memory");
            asm volatile("red.global.add.v4.f32 [%0], {%1,%2,%3,%4};"
                         :: "l"(sa), "f"(-h.x), "f"(-h.y), "f"(-h.z), "f"(-h.w) : "memory");

            // Rotate pipeline registers.
            e = en; s = sn; t = tn; wv = wvn; p1 = p1n; p2 = p2n;
        }
    }
}

// ---------------------------------------------------------------------------
// K3: out[b,n,:] = sigmoid(agg[b,n,:16] @ W_n[16,64] + b_n). Warp per node;
// lane owns cols {lane, lane+32}; packed fma2; MUFU sigmoid.
// ---------------------------------------------------------------------------
__global__ __launch_bounds__(256) void k3_nodes(
    const float* __restrict__ W_n, const float* __restrict__ b_n,
    float* __restrict__ out) {
    const int lane = threadIdx.x & 31;

    unsigned long long wA2[8], wB2[8];
#pragma unroll
    for (int j = 0; j < 8; j++) {
        wA2[j] = pack2(__ldg(W_n + (2 * j) * NO + lane),
                       __ldg(W_n + (2 * j + 1) * NO + lane));
        wB2[j] = pack2(__ldg(W_n + (2 * j) * NO + lane + 32),
                       __ldg(W_n + (2 * j + 1) * NO + lane + 32));
    }
    const float bA = __ldg(b_n + lane);
    const float bB = __ldg(b_n + lane + 32);

    const int tid    = blockIdx.x * blockDim.x + threadIdx.x;
    const int warpId = tid >> 5;
    const int nwarps = (gridDim.x * blockDim.x) >> 5;

    for (int node = warpId; node < Bb * Nn; node += nwarps) {
        const float* ag = g_agg + (size_t)node * 16;
        unsigned long long a[8];
#pragma unroll
        for (int j = 0; j < 4; j++)
            asm volatile("ld.global.nc.v2.b64 {%0, %1}, [%2];"
                         : "=l"(a[2 * j]), "=l"(a[2 * j + 1])
                         : "l"(ag + 4 * j));

        unsigned long long accA = 0ull, accB = 0ull;
#pragma unroll
        for (int j = 0; j < 8; j++) {
            accA = fma2(a[j], wA2[j], accA);
            accB = fma2(a[j], wB2[j], accB);
        }
        float2 sA = unpack2(accA), sB = unpack2(accB);
        out[(size_t)node * NO + lane]      = sigmoid_mufu(bA + sA.x + sA.y);
        out[(size_t)node * NO + lane + 32] = sigmoid_mufu(bB + sB.x + sB.y);
    }
}

// ---------------------------------------------------------------------------
extern "C" void kernel_launch(void* const* d_in, const int* in_sizes, int n_in,
                              void* d_out, int out_size) {
    const float* x    = (const float*)d_in[0];
    const int*   esrc = (const int*)d_in[1];
    const int*   etgt = (const int*)d_in[2];
    const float* ew   = (const float*)d_in[3];
    const float* W_e  = (const float*)d_in[4];
    const float* b_e  = (const float*)d_in[5];
    const float* W_n  = (const float*)d_in[6];
    const float* b_n  = (const float*)d_in[7];
    float* out = (float*)d_out;

    k1_precompute<<<148 * 16, 128>>>(x, W_e);
    k2_edges<<<148 * 8, 256>>>(esrc, etgt, ew, W_e, b_e);
    k3_nodes<<<148 * 8, 256>>>(W_n, b_n, out);
}